// round 15
// baseline (speedup 1.0000x reference)
#include <cuda_runtime.h>
#include <cuda_fp16.h>
#include <cstdint>

#define LQv 2048
#define BZv 8
#define Dv 1024
#define NHv 16
#define NKv 4
#define FFv 2048
#define HDv 64
#define MROWS (LQv * BZv)   // 16384

// ================= scratch =================
#define MDsz ((size_t)MROWS * Dv)
// float blob
#define OFF_OFFA  ((size_t)0)                            // [MROWS,128]
#define OFF_Y     (OFF_OFFA + (size_t)MROWS * 128)
#define OFF_BOFA  (OFF_Y   + MDsz)                       // [128]
#define SCRATCH_F (OFF_BOFA + 128)
__device__ float g_scratch_f[SCRATCH_F];

// half blob (all offsets multiples of 8 -> 16B aligned)
#define HOFF_SRC   ((size_t)0)
#define HOFF_VAL   (HOFF_SRC + MDsz)
#define HOFF_AO    (HOFF_VAL + MDsz)
#define HOFF_XH    (HOFF_AO  + MDsz)
#define HOFF_H     (HOFF_XH  + MDsz)                     // [MROWS,FF]
#define HOFF_WV    (HOFF_H   + (size_t)MROWS * FFv)
#define HOFF_WO    (HOFF_WV  + (size_t)Dv * Dv)
#define HOFF_W1    (HOFF_WO  + (size_t)Dv * Dv)
#define HOFF_W2    (HOFF_W1  + (size_t)Dv * FFv)
#define HOFF_WOFA  (HOFF_W2  + (size_t)FFv * Dv)         // [1024,128]
#define SCRATCH_H  (HOFF_WOFA + (size_t)Dv * 128)
__device__ __half g_scratch_h[SCRATCH_H];

__device__ __forceinline__ uint32_t smem_u32(const void* p) {
    uint32_t a;
    asm("{ .reg .u64 t; cvta.to.shared.u64 t, %1; cvt.u32.u64 %0, t; }"
        : "=r"(a) : "l"(p));
    return a;
}

#define CP16(dst, src) \
    asm volatile("cp.async.cg.shared.global [%0], [%1], 16;" \
                 :: "r"(dst), "l"(src))
#define CP_COMMIT() asm volatile("cp.async.commit_group;")
#define CP_WAIT1()  asm volatile("cp.async.wait_group 1;")
#define CP_WAIT0()  asm volatile("cp.async.wait_group 0;")

#define LDSM_X4(r, addr) \
    asm volatile("ldmatrix.sync.aligned.m8n8.x4.shared.b16 {%0,%1,%2,%3}, [%4];" \
                 : "=r"((r)[0]), "=r"((r)[1]), "=r"((r)[2]), "=r"((r)[3]) \
                 : "r"(addr))
#define LDSM_X4_T(r, addr) \
    asm volatile("ldmatrix.sync.aligned.m8n8.x4.trans.shared.b16 {%0,%1,%2,%3}, [%4];" \
                 : "=r"((r)[0]), "=r"((r)[1]), "=r"((r)[2]), "=r"((r)[3]) \
                 : "r"(addr))

__device__ __forceinline__ void mma_f16(float* c, const uint32_t* a,
                                        const uint32_t* b)
{
    asm volatile(
        "mma.sync.aligned.m16n8k16.row.col.f32.f16.f16.f32 "
        "{%0,%1,%2,%3}, {%4,%5,%6,%7}, {%8,%9}, {%0,%1,%2,%3};"
        : "+f"(c[0]), "+f"(c[1]), "+f"(c[2]), "+f"(c[3])
        : "r"(a[0]), "r"(a[1]), "r"(a[2]), "r"(a[3]),
          "r"(b[0]), "r"(b[1]));
}

// ================= fp32 -> fp16 convert (8 elems/thread) =================
__global__ __launch_bounds__(256)
void tohalf_k(const float* __restrict__ a, __half* __restrict__ o)
{
    size_t i = ((size_t)blockIdx.x * 256 + threadIdx.x) * 8;
    float4 v0 = *reinterpret_cast<const float4*>(a + i);
    float4 v1 = *reinterpret_cast<const float4*>(a + i + 4);
    __half2 h[4];
    h[0] = __floats2half2_rn(v0.x, v0.y);
    h[1] = __floats2half2_rn(v0.z, v0.w);
    h[2] = __floats2half2_rn(v1.x, v1.y);
    h[3] = __floats2half2_rn(v1.z, v1.w);
    *reinterpret_cast<uint4*>(o + i) = *reinterpret_cast<uint4*>(h);
}

// fuse Woff|Wa -> Wofa[1024][128] half + bias concat
__global__ __launch_bounds__(256)
void prep_offa_k(const float* __restrict__ Woff, const float* __restrict__ boff,
                 const float* __restrict__ Wa,   const float* __restrict__ ba,
                 __half* __restrict__ Wofa, float* __restrict__ bout)
{
    int idx = blockIdx.x * 256 + threadIdx.x;   // 1024*128
    int k = idx >> 7, n = idx & 127;
    float v = (n < 64) ? Woff[(size_t)k * 64 + n] : Wa[(size_t)k * 64 + (n - 64)];
    Wofa[idx] = __float2half(v);
    if (idx < 128) bout[idx] = (idx < 64) ? boff[idx] : ba[idx - 64];
}

// ================= fp16 mma GEMM, BK=64 =================
enum { EPI_BIAS = 0, EPI_MASK = 1, EPI_RELU = 2, EPI_RES = 3 };

#define SA_H 72                    // A row stride in halfs (144B)
#define SB_H 136                   // B row stride in halfs (272B)
#define A_B (128 * SA_H * 2)       // 18432 B
#define B_B (64 * SB_H * 2)        // 17408 B
#define STG_B (A_B + B_B)          // 35840 B
#define GSMEM_BYTES (3 * STG_B)    // 107520 B

template <int EPI, int OUTH, int RESH>
__global__ __launch_bounds__(256, 2)
void hmma_gemm(const __half* __restrict__ A, const __half* __restrict__ B,
               const float* __restrict__ bias, const void* __restrict__ resv,
               const unsigned char* __restrict__ mask,
               int K, int N, void* __restrict__ Cv)
{
    extern __shared__ char sm[];
    const uint32_t sb0 = smem_u32(sm);

    const int tid = threadIdx.x;
    const int lane = tid & 31;
    const int wid = tid >> 5;
    const int warp_m = wid & 1;
    const int warp_n = wid >> 1;
    const int g = lane >> 2, t = lane & 3;
    const int row0 = blockIdx.y * 128;
    const int col0 = blockIdx.x * 128;

    float acc[4][4][4];
#pragma unroll
    for (int mi = 0; mi < 4; mi++)
#pragma unroll
        for (int ni = 0; ni < 4; ni++)
#pragma unroll
            for (int j = 0; j < 4; j++) acc[mi][ni][j] = 0.f;

    const int NC = K >> 6;

    auto issue = [&](int c_, int s_) {
        const __half* Ap = A + (size_t)row0 * K + (c_ << 6);
        const __half* Bp = B + (size_t)(c_ << 6) * N + col0;
        uint32_t ab = sb0 + (uint32_t)s_ * STG_B;
        uint32_t bb = ab + A_B;
#pragma unroll
        for (int it = 0; it < 4; it++) {
            int id = tid + it * 256;
            int m = id >> 3, kc = id & 7;
            CP16(ab + (uint32_t)(m * (SA_H * 2) + kc * 16),
                 Ap + (size_t)m * K + kc * 8);
        }
#pragma unroll
        for (int it = 0; it < 4; it++) {
            int id = tid + it * 256;
            int k = id >> 4, nc = id & 15;
            CP16(bb + (uint32_t)(k * (SB_H * 2) + nc * 16),
                 Bp + (size_t)k * N + nc * 8);
        }
        CP_COMMIT();
    };

    const int rowA = (lane & 7) + 8 * ((lane >> 3) & 1);
    const int koffA = (lane >> 4) * 16;
    const int krowB = lane & 15;
    const int noffB = (lane >> 4) * 8;

    issue(0, 0);
    issue(1, 1);

    for (int c = 0; c < NC; c++) {
        const int s = c % 3;
        if (c + 2 < NC) { CP_WAIT1(); } else { CP_WAIT0(); }
        __syncthreads();
        if (c + 2 < NC) issue(c + 2, (c + 2) % 3);

        const uint32_t ab = sb0 + (uint32_t)s * STG_B;
        const uint32_t bb = ab + A_B;
#pragma unroll
        for (int kk = 0; kk < 4; kk++) {
            uint32_t af[4][4], bf[4][2];
#pragma unroll
            for (int mi = 0; mi < 4; mi++) {
                uint32_t addr = ab +
                    (uint32_t)((warp_m * 64 + mi * 16 + rowA) * (SA_H * 2) +
                               kk * 32 + koffA);
                LDSM_X4(af[mi], addr);
            }
#pragma unroll
            for (int ni2 = 0; ni2 < 2; ni2++) {
                uint32_t r[4];
                uint32_t addr = bb +
                    (uint32_t)((kk * 16 + krowB) * (SB_H * 2) +
                               (warp_n * 32 + ni2 * 16 + noffB) * 2);
                LDSM_X4_T(r, addr);
                bf[ni2 * 2 + 0][0] = r[0]; bf[ni2 * 2 + 0][1] = r[1];
                bf[ni2 * 2 + 1][0] = r[2]; bf[ni2 * 2 + 1][1] = r[3];
            }
#pragma unroll
            for (int mi = 0; mi < 4; mi++)
#pragma unroll
                for (int ni = 0; ni < 4; ni++)
                    mma_f16(acc[mi][ni], af[mi], bf[ni]);
        }
    }

    // ---- epilogue ----
#pragma unroll
    for (int mi = 0; mi < 4; mi++) {
        int rA = row0 + warp_m * 64 + mi * 16 + g;
#pragma unroll
        for (int half_i = 0; half_i < 2; half_i++) {
            int r = rA + half_i * 8;
            unsigned char mrow = 0;
            if (EPI == EPI_MASK) {
                int b = r & (BZv - 1);
                int qq = r >> 3;
                mrow = mask[b * LQv + qq];
            }
#pragma unroll
            for (int ni = 0; ni < 4; ni++) {
                int cc = col0 + warp_n * 32 + ni * 8 + t * 2;
                float v0 = acc[mi][ni][half_i * 2 + 0] + bias[cc + 0];
                float v1 = acc[mi][ni][half_i * 2 + 1] + bias[cc + 1];
                if (EPI == EPI_MASK && mrow) { v0 = 0.f; v1 = 0.f; }
                if (EPI == EPI_RELU) { v0 = fmaxf(v0, 0.f); v1 = fmaxf(v1, 0.f); }
                if (EPI == EPI_RES) {
                    if (RESH) {
                        __half2 rv = *reinterpret_cast<const __half2*>(
                            (const __half*)resv + (size_t)r * N + cc);
                        v0 += __half2float(rv.x); v1 += __half2float(rv.y);
                    } else {
                        float2 rv = *reinterpret_cast<const float2*>(
                            (const float*)resv + (size_t)r * N + cc);
                        v0 += rv.x; v1 += rv.y;
                    }
                }
                if (OUTH) {
                    __half2 h = __floats2half2_rn(v0, v1);
                    *reinterpret_cast<__half2*>(
                        (__half*)Cv + (size_t)r * N + cc) = h;
                } else {
                    *reinterpret_cast<float2*>(
                        (float*)Cv + (size_t)r * N + cc) = make_float2(v0, v1);
                }
            }
        }
    }
}

// ================= dedicated offa GEMM: q = src+pos staged inline ==========
// C[MROWS,128] = (src+pos) @ Wofa + bofa. BM=128, N=128, BK=64, single-buffer.
__global__ __launch_bounds__(256, 2)
void offa_gemm(const float* __restrict__ src, const float* __restrict__ pos,
               const __half* __restrict__ B,      // Wofa [1024][128]
               const float* __restrict__ bias, float* __restrict__ C)
{
    __shared__ __half As[128 * SA_H];
    __shared__ __half Bs[64 * SB_H];
    const uint32_t asb = smem_u32(As);
    const uint32_t bsb = smem_u32(Bs);

    const int tid = threadIdx.x;
    const int lane = tid & 31;
    const int wid = tid >> 5;
    const int warp_m = wid & 1;
    const int warp_n = wid >> 1;
    const int g = lane >> 2, t = lane & 3;
    const int row0 = blockIdx.x * 128;

    float acc[4][4][4];
#pragma unroll
    for (int mi = 0; mi < 4; mi++)
#pragma unroll
        for (int ni = 0; ni < 4; ni++)
#pragma unroll
            for (int j = 0; j < 4; j++) acc[mi][ni][j] = 0.f;

    const int rowA = (lane & 7) + 8 * ((lane >> 3) & 1);
    const int koffA = (lane >> 4) * 16;
    const int krowB = lane & 15;
    const int noffB = (lane >> 4) * 8;

    for (int c = 0; c < 16; c++) {          // K=1024 in BK=64 chunks
        // stage A: q = src+pos, fp32 -> fp16 (64 halfs per row)
#pragma unroll
        for (int it = 0; it < 4; it++) {
            int id = tid + it * 256;
            int m = id >> 3, kc = id & 7;
            size_t gi = (size_t)(row0 + m) * Dv + (c << 6) + kc * 8;
            float4 s0 = *reinterpret_cast<const float4*>(src + gi);
            float4 s1 = *reinterpret_cast<const float4*>(src + gi + 4);
            float4 p0 = *reinterpret_cast<const float4*>(pos + gi);
            float4 p1 = *reinterpret_cast<const float4*>(pos + gi + 4);
            __half2 h[4];
            h[0] = __floats2half2_rn(s0.x + p0.x, s0.y + p0.y);
            h[1] = __floats2half2_rn(s0.z + p0.z, s0.w + p0.w);
            h[2] = __floats2half2_rn(s1.x + p1.x, s1.y + p1.y);
            h[3] = __floats2half2_rn(s1.z + p1.z, s1.w + p1.w);
            *reinterpret_cast<uint4*>(&As[m * SA_H + kc * 8]) =
                *reinterpret_cast<uint4*>(h);
        }
        // stage B (already half): 64 rows x 16 granules of 8 halfs
#pragma unroll
        for (int it = 0; it < 4; it++) {
            int id = tid + it * 256;
            int k = id >> 4, nc = id & 15;
            *reinterpret_cast<uint4*>(&Bs[k * SB_H + nc * 8]) =
                *reinterpret_cast<const uint4*>(
                    B + (size_t)((c << 6) + k) * 128 + nc * 8);
        }
        __syncthreads();

#pragma unroll
        for (int kk = 0; kk < 4; kk++) {
            uint32_t af[4][4], bf[4][2];
#pragma unroll
            for (int mi = 0; mi < 4; mi++) {
                uint32_t addr = asb +
                    (uint32_t)((warp_m * 64 + mi * 16 + rowA) * (SA_H * 2) +
                               kk * 32 + koffA);
                LDSM_X4(af[mi], addr);
            }
#pragma unroll
            for (int ni2 = 0; ni2 < 2; ni2++) {
                uint32_t r[4];
                uint32_t addr = bsb +
                    (uint32_t)((kk * 16 + krowB) * (SB_H * 2) +
                               (warp_n * 32 + ni2 * 16 + noffB) * 2);
                LDSM_X4_T(r, addr);
                bf[ni2 * 2 + 0][0] = r[0]; bf[ni2 * 2 + 0][1] = r[1];
                bf[ni2 * 2 + 1][0] = r[2]; bf[ni2 * 2 + 1][1] = r[3];
            }
#pragma unroll
            for (int mi = 0; mi < 4; mi++)
#pragma unroll
                for (int ni = 0; ni < 4; ni++)
                    mma_f16(acc[mi][ni], af[mi], bf[ni]);
        }
        __syncthreads();
    }

#pragma unroll
    for (int mi = 0; mi < 4; mi++) {
        int rA = row0 + warp_m * 64 + mi * 16 + g;
#pragma unroll
        for (int half_i = 0; half_i < 2; half_i++) {
            int r = rA + half_i * 8;
#pragma unroll
            for (int ni = 0; ni < 4; ni++) {
                int cc = warp_n * 32 + ni * 8 + t * 2;
                float v0 = acc[mi][ni][half_i * 2 + 0] + bias[cc + 0];
                float v1 = acc[mi][ni][half_i * 2 + 1] + bias[cc + 1];
                *reinterpret_cast<float2*>(&C[(size_t)r * 128 + cc]) =
                    make_float2(v0, v1);
            }
        }
    }
}

// ================= softmax + grid_sample1d + head combine =================
__global__ __launch_bounds__(256)
void sample_k(const __half* __restrict__ value,
              const float* __restrict__ offa,
              const float* __restrict__ refp,
              const float* __restrict__ snip,
              __half* __restrict__ out)
{
    int t = blockIdx.x * 256 + threadIdx.x;
    int c = t & 63;
    int gidx = t >> 6;
    int h = gidx & (NHv - 1);
    int rb = gidx >> 4;
    int b = rb & (BZv - 1);
    int q = rb >> 3;

    const float* ol = offa + (size_t)rb * 128 + h * NKv;
    const float* al = ol + 64;

    float a0 = al[0], a1 = al[1], a2 = al[2], a3 = al[3];
    float m = fmaxf(fmaxf(a0, a1), fmaxf(a2, a3));
    float e0 = __expf(a0 - m), e1 = __expf(a1 - m);
    float e2 = __expf(a2 - m), e3 = __expf(a3 - m);
    float inv_s = 1.f / (e0 + e1 + e2 + e3);
    float ak[4] = {e0 * inv_s, e1 * inv_s, e2 * inv_s, e3 * inv_s};

    float refv = refp[b * LQv + q];
    float inv_sn = 1.f / snip[b];

    float acc = 0.f;
#pragma unroll
    for (int k = 0; k < NKv; k++) {
        float loc = refv + ol[k] * inv_sn;
        float x = loc * (float)(LQv - 1);
        float x0f = floorf(x);
        float w1 = x - x0f;
        float w0 = 1.f - w1;
        float x0c = fminf(fmaxf(x0f, -2.f), (float)(LQv + 1));
        int i0 = (int)x0c;
        int i1 = i0 + 1;
        float v0 = 0.f, v1 = 0.f;
        if (x0f >= 0.f && x0f <= (float)(LQv - 1))
            v0 = __half2float(value[((size_t)i0 * BZv + b) * Dv + h * HDv + c]);
        if (x0f >= -1.f && x0f <= (float)(LQv - 2))
            v1 = __half2float(value[((size_t)i1 * BZv + b) * Dv + h * HDv + c]);
        acc += ak[k] * (w0 * v0 + w1 * v1);
    }
    out[(size_t)rb * Dv + h * HDv + c] = __float2half(acc);
}

// ================= LayerNorm D=1024 (nullable fp32/fp16 outputs) ==========
__global__ __launch_bounds__(256)
void ln_k(const float* __restrict__ in, const float* __restrict__ gam,
          const float* __restrict__ bet, float* __restrict__ out,
          __half* __restrict__ out_h)
{
    int row = blockIdx.x;
    const float* xp = in + (size_t)row * Dv;
    int c4 = threadIdx.x * 4;
    float4 v = *reinterpret_cast<const float4*>(&xp[c4]);
    float s  = v.x + v.y + v.z + v.w;
    float ss = v.x * v.x + v.y * v.y + v.z * v.z + v.w * v.w;
#pragma unroll
    for (int o = 16; o > 0; o >>= 1) {
        s  += __shfl_xor_sync(0xffffffffu, s, o);
        ss += __shfl_xor_sync(0xffffffffu, ss, o);
    }
    __shared__ float sh_s[8], sh_ss[8];
    int w = threadIdx.x >> 5;
    if ((threadIdx.x & 31) == 0) { sh_s[w] = s; sh_ss[w] = ss; }
    __syncthreads();
    s = 0.f; ss = 0.f;
#pragma unroll
    for (int i = 0; i < 8; i++) { s += sh_s[i]; ss += sh_ss[i]; }
    float mean = s * (1.f / Dv);
    float var  = ss * (1.f / Dv) - mean * mean;
    float inv  = rsqrtf(var + 1e-5f);
    float4 gv = *reinterpret_cast<const float4*>(&gam[c4]);
    float4 bvv = *reinterpret_cast<const float4*>(&bet[c4]);
    float4 o;
    o.x = (v.x - mean) * inv * gv.x + bvv.x;
    o.y = (v.y - mean) * inv * gv.y + bvv.y;
    o.z = (v.z - mean) * inv * gv.z + bvv.z;
    o.w = (v.w - mean) * inv * gv.w + bvv.w;
    if (out)
        *reinterpret_cast<float4*>(&out[(size_t)row * Dv + c4]) = o;
    if (out_h) {
        __half2 h[2];
        h[0] = __floats2half2_rn(o.x, o.y);
        h[1] = __floats2half2_rn(o.z, o.w);
        *reinterpret_cast<uint2*>(&out_h[(size_t)row * Dv + c4]) =
            *reinterpret_cast<uint2*>(h);
    }
}

// ================= launch =================
extern "C" void kernel_launch(void* const* d_in, const int* in_sizes, int n_in,
                              void* d_out, int out_size)
{
    const float* src  = (const float*)d_in[0];
    const float* pos  = (const float*)d_in[1];
    const unsigned char* mask = (const unsigned char*)d_in[2];
    const float* refp = (const float*)d_in[3];
    const float* snip = (const float*)d_in[4];
    const float* Wv   = (const float*)d_in[5];
    const float* bv   = (const float*)d_in[6];
    const float* Woff = (const float*)d_in[7];
    const float* boff = (const float*)d_in[8];
    const float* Wa   = (const float*)d_in[9];
    const float* ba   = (const float*)d_in[10];
    const float* Wo   = (const float*)d_in[11];
    const float* bo   = (const float*)d_in[12];
    const float* W1   = (const float*)d_in[13];
    const float* b1   = (const float*)d_in[14];
    const float* W2   = (const float*)d_in[15];
    const float* b2   = (const float*)d_in[16];
    const float* g1   = (const float*)d_in[17];
    const float* be1  = (const float*)d_in[18];
    const float* g2   = (const float*)d_in[19];
    const float* be2  = (const float*)d_in[20];
    float* outp = (float*)d_out;

    float* sf = nullptr;
    __half* sh = nullptr;
    cudaGetSymbolAddress((void**)&sf, g_scratch_f);
    cudaGetSymbolAddress((void**)&sh, g_scratch_h);
    float* offa = sf + OFF_OFFA;
    float* y    = sf + OFF_Y;
    float* bofa = sf + OFF_BOFA;
    __half* srch = sh + HOFF_SRC;
    __half* valh = sh + HOFF_VAL;
    __half* aoh  = sh + HOFF_AO;
    __half* xh   = sh + HOFF_XH;
    __half* hh   = sh + HOFF_H;
    __half* wvh  = sh + HOFF_WV;
    __half* woh  = sh + HOFF_WO;
    __half* w1h  = sh + HOFF_W1;
    __half* w2h  = sh + HOFF_W2;
    __half* wofah = sh + HOFF_WOFA;

    static cudaStream_t s_aux = nullptr;
    static cudaEvent_t ev_root, ev_wv, ev_offa, ev_w;
    if (!s_aux) {
        cudaStreamCreateWithFlags(&s_aux, cudaStreamNonBlocking);
        cudaEventCreateWithFlags(&ev_root, cudaEventDisableTiming);
        cudaEventCreateWithFlags(&ev_wv,   cudaEventDisableTiming);
        cudaEventCreateWithFlags(&ev_offa, cudaEventDisableTiming);
        cudaEventCreateWithFlags(&ev_w,    cudaEventDisableTiming);
        cudaFuncSetAttribute(hmma_gemm<EPI_MASK, 1, 0>,
            cudaFuncAttributeMaxDynamicSharedMemorySize, GSMEM_BYTES);
        cudaFuncSetAttribute(hmma_gemm<EPI_RELU, 1, 0>,
            cudaFuncAttributeMaxDynamicSharedMemorySize, GSMEM_BYTES);
        cudaFuncSetAttribute(hmma_gemm<EPI_RES, 0, 0>,
            cudaFuncAttributeMaxDynamicSharedMemorySize, GSMEM_BYTES);
        cudaFuncSetAttribute(hmma_gemm<EPI_RES, 0, 1>,
            cudaFuncAttributeMaxDynamicSharedMemorySize, GSMEM_BYTES);
    }

    const dim3 blk(256);

    // fork
    cudaEventRecord(ev_root, 0);
    cudaStreamWaitEvent(s_aux, ev_root, 0);

    // main: srch = half(src)
    tohalf_k<<<(MDsz / 8) / 256, blk>>>(src, srch);

    // aux: fully independent chain, never idles
    tohalf_k<<<((size_t)Dv * Dv / 8) / 256, blk, 0, s_aux>>>(Wv, wvh);
    cudaEventRecord(ev_wv, s_aux);
    prep_offa_k<<<(Dv * 128) / 256, blk, 0, s_aux>>>(Woff, boff, Wa, ba,
                                                     wofah, bofa);
    offa_gemm<<<MROWS / 128, blk, 0, s_aux>>>(src, pos, wofah, bofa, offa);
    cudaEventRecord(ev_offa, s_aux);
    tohalf_k<<<((size_t)Dv * Dv / 8) / 256, blk, 0, s_aux>>>(Wo, woh);
    tohalf_k<<<((size_t)Dv * FFv / 8) / 256, blk, 0, s_aux>>>(W1, w1h);
    tohalf_k<<<((size_t)FFv * Dv / 8) / 256, blk, 0, s_aux>>>(W2, w2h);
    cudaEventRecord(ev_w, s_aux);

    // main: value GEMM (needs srch + wvh)
    cudaStreamWaitEvent(0, ev_wv, 0);
    hmma_gemm<EPI_MASK, 1, 0><<<dim3(Dv / 128, MROWS / 128), blk,
                                GSMEM_BYTES>>>(
        srch, wvh, bv, nullptr, mask, Dv, Dv, valh);

    // main: sample (needs valh + offa)
    cudaStreamWaitEvent(0, ev_offa, 0);
    sample_k<<<(size_t)MROWS * NHv * HDv / 256, blk>>>(valh, offa, refp,
                                                       snip, aoh);

    // main: out proj + residual(src fp32) -> y, LN1 (xh only)
    cudaStreamWaitEvent(0, ev_w, 0);
    hmma_gemm<EPI_RES, 0, 0><<<dim3(Dv / 128, MROWS / 128), blk,
                               GSMEM_BYTES>>>(
        aoh, woh, bo, src, nullptr, Dv, Dv, y);
    ln_k<<<MROWS, blk>>>(y, g1, be1, nullptr, xh);

    // FFN (W2 residual = xh, half)
    hmma_gemm<EPI_RELU, 1, 0><<<dim3(FFv / 128, MROWS / 128), blk,
                                GSMEM_BYTES>>>(
        xh, w1h, b1, nullptr, nullptr, Dv, FFv, hh);
    hmma_gemm<EPI_RES, 0, 1><<<dim3(Dv / 128, MROWS / 128), blk,
                               GSMEM_BYTES>>>(
        hh, w2h, b2, xh, nullptr, FFv, Dv, y);
    ln_k<<<MROWS, blk>>>(y, g2, be2, outp, nullptr);
}

// round 17
// speedup vs baseline: 1.0376x; 1.0376x over previous
#include <cuda_runtime.h>
#include <cuda_fp16.h>
#include <cstdint>

#define LQv 2048
#define BZv 8
#define Dv 1024
#define NHv 16
#define NKv 4
#define FFv 2048
#define HDv 64
#define MROWS (LQv * BZv)   // 16384

// ================= scratch =================
#define MDsz ((size_t)MROWS * Dv)
// float blob
#define OFF_OFFA  ((size_t)0)                            // [MROWS,128]
#define OFF_Y     (OFF_OFFA + (size_t)MROWS * 128)
#define OFF_BOFA  (OFF_Y   + MDsz)                       // [128]
#define SCRATCH_F (OFF_BOFA + 128)
__device__ float g_scratch_f[SCRATCH_F];

// half blob (all offsets multiples of 8 -> 16B aligned)
#define HOFF_SRC   ((size_t)0)
#define HOFF_Q     (HOFF_SRC + MDsz)
#define HOFF_VAL   (HOFF_Q   + MDsz)
#define HOFF_AO    (HOFF_VAL + MDsz)
#define HOFF_XH    (HOFF_AO  + MDsz)
#define HOFF_H     (HOFF_XH  + MDsz)                     // [MROWS,FF]
#define HOFF_WV    (HOFF_H   + (size_t)MROWS * FFv)
#define HOFF_WO    (HOFF_WV  + (size_t)Dv * Dv)
#define HOFF_W1    (HOFF_WO  + (size_t)Dv * Dv)
#define HOFF_W2    (HOFF_W1  + (size_t)Dv * FFv)
#define HOFF_WOFA  (HOFF_W2  + (size_t)FFv * Dv)         // [1024,128]
#define SCRATCH_H  (HOFF_WOFA + (size_t)Dv * 128)
__device__ __half g_scratch_h[SCRATCH_H];

__device__ __forceinline__ uint32_t smem_u32(const void* p) {
    uint32_t a;
    asm("{ .reg .u64 t; cvta.to.shared.u64 t, %1; cvt.u32.u64 %0, t; }"
        : "=r"(a) : "l"(p));
    return a;
}

#define CP16(dst, src) \
    asm volatile("cp.async.cg.shared.global [%0], [%1], 16;" \
                 :: "r"(dst), "l"(src))
#define CP_COMMIT() asm volatile("cp.async.commit_group;")
#define CP_WAIT1()  asm volatile("cp.async.wait_group 1;")
#define CP_WAIT0()  asm volatile("cp.async.wait_group 0;")

#define LDSM_X4(r, addr) \
    asm volatile("ldmatrix.sync.aligned.m8n8.x4.shared.b16 {%0,%1,%2,%3}, [%4];" \
                 : "=r"((r)[0]), "=r"((r)[1]), "=r"((r)[2]), "=r"((r)[3]) \
                 : "r"(addr))
#define LDSM_X4_T(r, addr) \
    asm volatile("ldmatrix.sync.aligned.m8n8.x4.trans.shared.b16 {%0,%1,%2,%3}, [%4];" \
                 : "=r"((r)[0]), "=r"((r)[1]), "=r"((r)[2]), "=r"((r)[3]) \
                 : "r"(addr))

__device__ __forceinline__ void mma_f16(float* c, const uint32_t* a,
                                        const uint32_t* b)
{
    asm volatile(
        "mma.sync.aligned.m16n8k16.row.col.f32.f16.f16.f32 "
        "{%0,%1,%2,%3}, {%4,%5,%6,%7}, {%8,%9}, {%0,%1,%2,%3};"
        : "+f"(c[0]), "+f"(c[1]), "+f"(c[2]), "+f"(c[3])
        : "r"(a[0]), "r"(a[1]), "r"(a[2]), "r"(a[3]),
          "r"(b[0]), "r"(b[1]));
}

// ================= fp32 -> fp16 convert (8 elems/thread) =================
__global__ __launch_bounds__(256)
void tohalf_k(const float* __restrict__ a, __half* __restrict__ o)
{
    size_t i = ((size_t)blockIdx.x * 256 + threadIdx.x) * 8;
    float4 v0 = *reinterpret_cast<const float4*>(a + i);
    float4 v1 = *reinterpret_cast<const float4*>(a + i + 4);
    __half2 h[4];
    h[0] = __floats2half2_rn(v0.x, v0.y);
    h[1] = __floats2half2_rn(v0.z, v0.w);
    h[2] = __floats2half2_rn(v1.x, v1.y);
    h[3] = __floats2half2_rn(v1.z, v1.w);
    *reinterpret_cast<uint4*>(o + i) = *reinterpret_cast<uint4*>(h);
}

// fused: srch = half(src); qh = half(src + pos)  (one read of src)
__global__ __launch_bounds__(256)
void srcq_k(const float* __restrict__ src, const float* __restrict__ pos,
            __half* __restrict__ srch, __half* __restrict__ qh)
{
    size_t i = ((size_t)blockIdx.x * 256 + threadIdx.x) * 8;
    float4 a0 = *reinterpret_cast<const float4*>(src + i);
    float4 a1 = *reinterpret_cast<const float4*>(src + i + 4);
    float4 b0 = *reinterpret_cast<const float4*>(pos + i);
    float4 b1 = *reinterpret_cast<const float4*>(pos + i + 4);
    __half2 hs[4], hq[4];
    hs[0] = __floats2half2_rn(a0.x, a0.y);
    hs[1] = __floats2half2_rn(a0.z, a0.w);
    hs[2] = __floats2half2_rn(a1.x, a1.y);
    hs[3] = __floats2half2_rn(a1.z, a1.w);
    hq[0] = __floats2half2_rn(a0.x + b0.x, a0.y + b0.y);
    hq[1] = __floats2half2_rn(a0.z + b0.z, a0.w + b0.w);
    hq[2] = __floats2half2_rn(a1.x + b1.x, a1.y + b1.y);
    hq[3] = __floats2half2_rn(a1.z + b1.z, a1.w + b1.w);
    *reinterpret_cast<uint4*>(srch + i) = *reinterpret_cast<uint4*>(hs);
    *reinterpret_cast<uint4*>(qh + i)   = *reinterpret_cast<uint4*>(hq);
}

// fuse Woff|Wa -> Wofa[1024][128] half + bias concat
__global__ __launch_bounds__(256)
void prep_offa_k(const float* __restrict__ Woff, const float* __restrict__ boff,
                 const float* __restrict__ Wa,   const float* __restrict__ ba,
                 __half* __restrict__ Wofa, float* __restrict__ bout)
{
    int idx = blockIdx.x * 256 + threadIdx.x;   // 1024*128
    int k = idx >> 7, n = idx & 127;
    float v = (n < 64) ? Woff[(size_t)k * 64 + n] : Wa[(size_t)k * 64 + (n - 64)];
    Wofa[idx] = __float2half(v);
    if (idx < 128) bout[idx] = (idx < 64) ? boff[idx] : ba[idx - 64];
}

// ================= fp16 mma GEMM, BK=64 =================
enum { EPI_BIAS = 0, EPI_MASK = 1, EPI_RELU = 2, EPI_RES = 3 };

#define SA_H 72                    // A row stride in halfs (144B)
#define SB_H 136                   // B row stride in halfs (272B)
#define A_B (128 * SA_H * 2)       // 18432 B
#define B_B (64 * SB_H * 2)        // 17408 B
#define STG_B (A_B + B_B)          // 35840 B
#define GSMEM_BYTES (3 * STG_B)    // 107520 B

template <int EPI, int OUTH, int RESH>
__global__ __launch_bounds__(256, 2)
void hmma_gemm(const __half* __restrict__ A, const __half* __restrict__ B,
               const float* __restrict__ bias, const void* __restrict__ resv,
               const unsigned char* __restrict__ mask,
               int K, int N, void* __restrict__ Cv)
{
    extern __shared__ char sm[];
    const uint32_t sb0 = smem_u32(sm);

    const int tid = threadIdx.x;
    const int lane = tid & 31;
    const int wid = tid >> 5;
    const int warp_m = wid & 1;
    const int warp_n = wid >> 1;
    const int g = lane >> 2, t = lane & 3;
    const int row0 = blockIdx.y * 128;
    const int col0 = blockIdx.x * 128;

    float acc[4][4][4];
#pragma unroll
    for (int mi = 0; mi < 4; mi++)
#pragma unroll
        for (int ni = 0; ni < 4; ni++)
#pragma unroll
            for (int j = 0; j < 4; j++) acc[mi][ni][j] = 0.f;

    const int NC = K >> 6;

    auto issue = [&](int c_, int s_) {
        const __half* Ap = A + (size_t)row0 * K + (c_ << 6);
        const __half* Bp = B + (size_t)(c_ << 6) * N + col0;
        uint32_t ab = sb0 + (uint32_t)s_ * STG_B;
        uint32_t bb = ab + A_B;
#pragma unroll
        for (int it = 0; it < 4; it++) {
            int id = tid + it * 256;
            int m = id >> 3, kc = id & 7;
            CP16(ab + (uint32_t)(m * (SA_H * 2) + kc * 16),
                 Ap + (size_t)m * K + kc * 8);
        }
#pragma unroll
        for (int it = 0; it < 4; it++) {
            int id = tid + it * 256;
            int k = id >> 4, nc = id & 15;
            CP16(bb + (uint32_t)(k * (SB_H * 2) + nc * 16),
                 Bp + (size_t)k * N + nc * 8);
        }
        CP_COMMIT();
    };

    const int rowA = (lane & 7) + 8 * ((lane >> 3) & 1);
    const int koffA = (lane >> 4) * 16;
    const int krowB = lane & 15;
    const int noffB = (lane >> 4) * 8;

    issue(0, 0);
    issue(1, 1);

    for (int c = 0; c < NC; c++) {
        const int s = c % 3;
        if (c + 2 < NC) { CP_WAIT1(); } else { CP_WAIT0(); }
        __syncthreads();
        if (c + 2 < NC) issue(c + 2, (c + 2) % 3);

        const uint32_t ab = sb0 + (uint32_t)s * STG_B;
        const uint32_t bb = ab + A_B;
#pragma unroll
        for (int kk = 0; kk < 4; kk++) {
            uint32_t af[4][4], bf[4][2];
#pragma unroll
            for (int mi = 0; mi < 4; mi++) {
                uint32_t addr = ab +
                    (uint32_t)((warp_m * 64 + mi * 16 + rowA) * (SA_H * 2) +
                               kk * 32 + koffA);
                LDSM_X4(af[mi], addr);
            }
#pragma unroll
            for (int ni2 = 0; ni2 < 2; ni2++) {
                uint32_t r[4];
                uint32_t addr = bb +
                    (uint32_t)((kk * 16 + krowB) * (SB_H * 2) +
                               (warp_n * 32 + ni2 * 16 + noffB) * 2);
                LDSM_X4_T(r, addr);
                bf[ni2 * 2 + 0][0] = r[0]; bf[ni2 * 2 + 0][1] = r[1];
                bf[ni2 * 2 + 1][0] = r[2]; bf[ni2 * 2 + 1][1] = r[3];
            }
#pragma unroll
            for (int mi = 0; mi < 4; mi++)
#pragma unroll
                for (int ni = 0; ni < 4; ni++)
                    mma_f16(acc[mi][ni], af[mi], bf[ni]);
        }
    }

    // ---- epilogue ----
#pragma unroll
    for (int mi = 0; mi < 4; mi++) {
        int rA = row0 + warp_m * 64 + mi * 16 + g;
#pragma unroll
        for (int half_i = 0; half_i < 2; half_i++) {
            int r = rA + half_i * 8;
            unsigned char mrow = 0;
            if (EPI == EPI_MASK) {
                int b = r & (BZv - 1);
                int qq = r >> 3;
                mrow = mask[b * LQv + qq];
            }
#pragma unroll
            for (int ni = 0; ni < 4; ni++) {
                int cc = col0 + warp_n * 32 + ni * 8 + t * 2;
                float v0 = acc[mi][ni][half_i * 2 + 0] + bias[cc + 0];
                float v1 = acc[mi][ni][half_i * 2 + 1] + bias[cc + 1];
                if (EPI == EPI_MASK && mrow) { v0 = 0.f; v1 = 0.f; }
                if (EPI == EPI_RELU) { v0 = fmaxf(v0, 0.f); v1 = fmaxf(v1, 0.f); }
                if (EPI == EPI_RES) {
                    if (RESH) {
                        __half2 rv = *reinterpret_cast<const __half2*>(
                            (const __half*)resv + (size_t)r * N + cc);
                        v0 += __half2float(rv.x); v1 += __half2float(rv.y);
                    } else {
                        float2 rv = *reinterpret_cast<const float2*>(
                            (const float*)resv + (size_t)r * N + cc);
                        v0 += rv.x; v1 += rv.y;
                    }
                }
                if (OUTH) {
                    __half2 h = __floats2half2_rn(v0, v1);
                    *reinterpret_cast<__half2*>(
                        (__half*)Cv + (size_t)r * N + cc) = h;
                } else {
                    *reinterpret_cast<float2*>(
                        (float*)Cv + (size_t)r * N + cc) = make_float2(v0, v1);
                }
            }
        }
    }
}

// ================= softmax + grid_sample1d + head combine =================
__global__ __launch_bounds__(256)
void sample_k(const __half* __restrict__ value,
              const float* __restrict__ offa,
              const float* __restrict__ refp,
              const float* __restrict__ snip,
              __half* __restrict__ out)
{
    int t = blockIdx.x * 256 + threadIdx.x;
    int c = t & 63;
    int gidx = t >> 6;
    int h = gidx & (NHv - 1);
    int rb = gidx >> 4;
    int b = rb & (BZv - 1);
    int q = rb >> 3;

    const float* ol = offa + (size_t)rb * 128 + h * NKv;
    const float* al = ol + 64;

    float a0 = al[0], a1 = al[1], a2 = al[2], a3 = al[3];
    float m = fmaxf(fmaxf(a0, a1), fmaxf(a2, a3));
    float e0 = __expf(a0 - m), e1 = __expf(a1 - m);
    float e2 = __expf(a2 - m), e3 = __expf(a3 - m);
    float inv_s = 1.f / (e0 + e1 + e2 + e3);
    float ak[4] = {e0 * inv_s, e1 * inv_s, e2 * inv_s, e3 * inv_s};

    float refv = refp[b * LQv + q];
    float inv_sn = 1.f / snip[b];

    float acc = 0.f;
#pragma unroll
    for (int k = 0; k < NKv; k++) {
        float loc = refv + ol[k] * inv_sn;
        float x = loc * (float)(LQv - 1);
        float x0f = floorf(x);
        float w1 = x - x0f;
        float w0 = 1.f - w1;
        float x0c = fminf(fmaxf(x0f, -2.f), (float)(LQv + 1));
        int i0 = (int)x0c;
        int i1 = i0 + 1;
        float v0 = 0.f, v1 = 0.f;
        if (x0f >= 0.f && x0f <= (float)(LQv - 1))
            v0 = __half2float(value[((size_t)i0 * BZv + b) * Dv + h * HDv + c]);
        if (x0f >= -1.f && x0f <= (float)(LQv - 2))
            v1 = __half2float(value[((size_t)i1 * BZv + b) * Dv + h * HDv + c]);
        acc += ak[k] * (w0 * v0 + w1 * v1);
    }
    out[(size_t)rb * Dv + h * HDv + c] = __float2half(acc);
}

// ================= LayerNorm D=1024 (nullable fp32/fp16 outputs) ==========
__global__ __launch_bounds__(256)
void ln_k(const float* __restrict__ in, const float* __restrict__ gam,
          const float* __restrict__ bet, float* __restrict__ out,
          __half* __restrict__ out_h)
{
    int row = blockIdx.x;
    const float* xp = in + (size_t)row * Dv;
    int c4 = threadIdx.x * 4;
    float4 v = *reinterpret_cast<const float4*>(&xp[c4]);
    float s  = v.x + v.y + v.z + v.w;
    float ss = v.x * v.x + v.y * v.y + v.z * v.z + v.w * v.w;
#pragma unroll
    for (int o = 16; o > 0; o >>= 1) {
        s  += __shfl_xor_sync(0xffffffffu, s, o);
        ss += __shfl_xor_sync(0xffffffffu, ss, o);
    }
    __shared__ float sh_s[8], sh_ss[8];
    int w = threadIdx.x >> 5;
    if ((threadIdx.x & 31) == 0) { sh_s[w] = s; sh_ss[w] = ss; }
    __syncthreads();
    s = 0.f; ss = 0.f;
#pragma unroll
    for (int i = 0; i < 8; i++) { s += sh_s[i]; ss += sh_ss[i]; }
    float mean = s * (1.f / Dv);
    float var  = ss * (1.f / Dv) - mean * mean;
    float inv  = rsqrtf(var + 1e-5f);
    float4 gv = *reinterpret_cast<const float4*>(&gam[c4]);
    float4 bvv = *reinterpret_cast<const float4*>(&bet[c4]);
    float4 o;
    o.x = (v.x - mean) * inv * gv.x + bvv.x;
    o.y = (v.y - mean) * inv * gv.y + bvv.y;
    o.z = (v.z - mean) * inv * gv.z + bvv.z;
    o.w = (v.w - mean) * inv * gv.w + bvv.w;
    if (out)
        *reinterpret_cast<float4*>(&out[(size_t)row * Dv + c4]) = o;
    if (out_h) {
        __half2 h[2];
        h[0] = __floats2half2_rn(o.x, o.y);
        h[1] = __floats2half2_rn(o.z, o.w);
        *reinterpret_cast<uint2*>(&out_h[(size_t)row * Dv + c4]) =
            *reinterpret_cast<uint2*>(h);
    }
}

// ================= launch =================
extern "C" void kernel_launch(void* const* d_in, const int* in_sizes, int n_in,
                              void* d_out, int out_size)
{
    const float* src  = (const float*)d_in[0];
    const float* pos  = (const float*)d_in[1];
    const unsigned char* mask = (const unsigned char*)d_in[2];
    const float* refp = (const float*)d_in[3];
    const float* snip = (const float*)d_in[4];
    const float* Wv   = (const float*)d_in[5];
    const float* bv   = (const float*)d_in[6];
    const float* Woff = (const float*)d_in[7];
    const float* boff = (const float*)d_in[8];
    const float* Wa   = (const float*)d_in[9];
    const float* ba   = (const float*)d_in[10];
    const float* Wo   = (const float*)d_in[11];
    const float* bo   = (const float*)d_in[12];
    const float* W1   = (const float*)d_in[13];
    const float* b1   = (const float*)d_in[14];
    const float* W2   = (const float*)d_in[15];
    const float* b2   = (const float*)d_in[16];
    const float* g1   = (const float*)d_in[17];
    const float* be1  = (const float*)d_in[18];
    const float* g2   = (const float*)d_in[19];
    const float* be2  = (const float*)d_in[20];
    float* outp = (float*)d_out;

    float* sf = nullptr;
    __half* sh = nullptr;
    cudaGetSymbolAddress((void**)&sf, g_scratch_f);
    cudaGetSymbolAddress((void**)&sh, g_scratch_h);
    float* offa = sf + OFF_OFFA;
    float* y    = sf + OFF_Y;
    float* bofa = sf + OFF_BOFA;
    __half* srch = sh + HOFF_SRC;
    __half* qh   = sh + HOFF_Q;
    __half* valh = sh + HOFF_VAL;
    __half* aoh  = sh + HOFF_AO;
    __half* xh   = sh + HOFF_XH;
    __half* hh   = sh + HOFF_H;
    __half* wvh  = sh + HOFF_WV;
    __half* woh  = sh + HOFF_WO;
    __half* w1h  = sh + HOFF_W1;
    __half* w2h  = sh + HOFF_W2;
    __half* wofah = sh + HOFF_WOFA;

    static cudaStream_t s_aux = nullptr;
    static cudaEvent_t ev_root, ev_q, ev_wv, ev_offa, ev_w;
    if (!s_aux) {
        cudaStreamCreateWithFlags(&s_aux, cudaStreamNonBlocking);
        cudaEventCreateWithFlags(&ev_root, cudaEventDisableTiming);
        cudaEventCreateWithFlags(&ev_q,    cudaEventDisableTiming);
        cudaEventCreateWithFlags(&ev_wv,   cudaEventDisableTiming);
        cudaEventCreateWithFlags(&ev_offa, cudaEventDisableTiming);
        cudaEventCreateWithFlags(&ev_w,    cudaEventDisableTiming);
        cudaFuncSetAttribute(hmma_gemm<EPI_MASK, 1, 0>,
            cudaFuncAttributeMaxDynamicSharedMemorySize, GSMEM_BYTES);
        cudaFuncSetAttribute(hmma_gemm<EPI_BIAS, 0, 0>,
            cudaFuncAttributeMaxDynamicSharedMemorySize, GSMEM_BYTES);
        cudaFuncSetAttribute(hmma_gemm<EPI_RELU, 1, 0>,
            cudaFuncAttributeMaxDynamicSharedMemorySize, GSMEM_BYTES);
        cudaFuncSetAttribute(hmma_gemm<EPI_RES, 0, 0>,
            cudaFuncAttributeMaxDynamicSharedMemorySize, GSMEM_BYTES);
        cudaFuncSetAttribute(hmma_gemm<EPI_RES, 0, 1>,
            cudaFuncAttributeMaxDynamicSharedMemorySize, GSMEM_BYTES);
    }

    const dim3 blk(256);

    // fork
    cudaEventRecord(ev_root, 0);
    cudaStreamWaitEvent(s_aux, ev_root, 0);

    // main: srch + qh (one pass over src/pos)
    srcq_k<<<(MDsz / 8) / 256, blk>>>(src, pos, srch, qh);
    cudaEventRecord(ev_q, 0);

    // aux: all weight conversions first (keeps aux busy during srcq),
    // then offa GEMM overlapping the value GEMM on main.
    tohalf_k<<<((size_t)Dv * Dv / 8) / 256, blk, 0, s_aux>>>(Wv, wvh);
    cudaEventRecord(ev_wv, s_aux);
    prep_offa_k<<<(Dv * 128) / 256, blk, 0, s_aux>>>(Woff, boff, Wa, ba,
                                                     wofah, bofa);
    tohalf_k<<<((size_t)Dv * Dv / 8) / 256, blk, 0, s_aux>>>(Wo, woh);
    tohalf_k<<<((size_t)Dv * FFv / 8) / 256, blk, 0, s_aux>>>(W1, w1h);
    tohalf_k<<<((size_t)FFv * Dv / 8) / 256, blk, 0, s_aux>>>(W2, w2h);
    cudaEventRecord(ev_w, s_aux);
    cudaStreamWaitEvent(s_aux, ev_q, 0);
    hmma_gemm<EPI_BIAS, 0, 0><<<dim3(1, MROWS / 128), blk, GSMEM_BYTES,
                                s_aux>>>(
        qh, wofah, bofa, nullptr, nullptr, Dv, 128, offa);
    cudaEventRecord(ev_offa, s_aux);

    // main: value GEMM (needs srch + wvh)
    cudaStreamWaitEvent(0, ev_wv, 0);
    hmma_gemm<EPI_MASK, 1, 0><<<dim3(Dv / 128, MROWS / 128), blk,
                                GSMEM_BYTES>>>(
        srch, wvh, bv, nullptr, mask, Dv, Dv, valh);

    // main: sample (needs valh + offa)
    cudaStreamWaitEvent(0, ev_offa, 0);
    sample_k<<<(size_t)MROWS * NHv * HDv / 256, blk>>>(valh, offa, refp,
                                                       snip, aoh);

    // main: out proj + residual(src fp32) -> y, LN1 (xh only)
    cudaStreamWaitEvent(0, ev_w, 0);
    hmma_gemm<EPI_RES, 0, 0><<<dim3(Dv / 128, MROWS / 128), blk,
                               GSMEM_BYTES>>>(
        aoh, woh, bo, src, nullptr, Dv, Dv, y);
    ln_k<<<MROWS, blk>>>(y, g1, be1, nullptr, xh);

    // FFN (W2 residual = xh, half)
    hmma_gemm<EPI_RELU, 1, 0><<<dim3(FFv / 128, MROWS / 128), blk,
                                GSMEM_BYTES>>>(
        xh, w1h, b1, nullptr, nullptr, Dv, FFv, hh);
    hmma_gemm<EPI_RES, 0, 1><<<dim3(Dv / 128, MROWS / 128), blk,
                               GSMEM_BYTES>>>(
        hh, w2h, b2, xh, nullptr, FFv, Dv, y);
    ln_k<<<MROWS, blk>>>(y, g2, be2, outp, nullptr);
}